// round 12
// baseline (speedup 1.0000x reference)
#include <cuda_runtime.h>
#include <cuda_fp16.h>
#include <math.h>
#include <stdio.h>
#include <stdint.h>

// ---------------- static problem capacities ----------------
#define MAXN 50000
#define MAXE 800000
#define HCn  256      // H*C
#define Hh   4
#define Cc   64
#define NG   64       // graphs
#define NA   32       // actions

// ---------------- device scratch (allocation-free rule) ----------------
__device__ __half g_ah[(size_t)MAXN * HCn];   // GEMM A input: x fp16, then h2 fp16
__device__ __half g_h [(size_t)MAXN * HCn];   // GEMM output (gather source)
__device__ __half g_w1t[256 * 128];           // W1^T fp16  [n][k]
__device__ __half g_w2t[256 * 256];           // W2^T fp16  [n][k]
__device__ float g_asrc[MAXN * Hh];
__device__ float g_adst[MAXN * Hh];
__device__ float g_hf  [(size_t)MAXN * Cc];   // final node features [N,64]
__device__ float g_pooled[NG * Cc];
__device__ int   g_start[NG];
__device__ int   g_end  [NG];
__device__ int   g_rowptr[MAXN + 1];
__device__ int   g_cursor[MAXN];
__device__ int   g_csr[MAXE];

// ---------------- helpers ----------------
__device__ __forceinline__ float lrelu(float x) { return fmaxf(x, 0.2f * x); }
__device__ __forceinline__ float elu1(float x)  { return x > 0.f ? x : expm1f(x); }

__device__ __forceinline__ void mma_f16(float4& c,
    uint32_t a0, uint32_t a1, uint32_t a2, uint32_t a3,
    uint32_t b0, uint32_t b1)
{
    asm volatile(
        "mma.sync.aligned.m16n8k16.row.col.f32.f16.f16.f32 "
        "{%0,%1,%2,%3}, {%4,%5,%6,%7}, {%8,%9}, {%0,%1,%2,%3};"
        : "+f"(c.x), "+f"(c.y), "+f"(c.z), "+f"(c.w)
        : "r"(a0), "r"(a1), "r"(a2), "r"(a3), "r"(b0), "r"(b1));
}

__device__ __forceinline__ void cp16(void* sm, const void* gm) {
    uint32_t sa = (uint32_t)__cvta_generic_to_shared(sm);
    asm volatile("cp.async.ca.shared.global [%0], [%1], 16;" :: "r"(sa), "l"(gm));
}
__device__ __forceinline__ void cp_commit() {
    asm volatile("cp.async.commit_group;" ::: "memory");
}
template <int Npend>
__device__ __forceinline__ void cp_wait() {
    asm volatile("cp.async.wait_group %0;" :: "n"(Npend) : "memory");
}

// ---------------- small utility kernels ----------------
__global__ void init_bounds_k(int* start, int* end, float* pooled) {
    int i = blockIdx.x * blockDim.x + threadIdx.x;
    if (i < NG) { start[i] = 1 << 30; end[i] = 0; }
    if (i < NG * Cc) pooled[i] = 0.f;
}

// x (fp32) -> fp16, vectorized 4-wide
__global__ void convert_x_k(const float* __restrict__ x, __half* __restrict__ xh, size_t n4) {
    size_t i = (size_t)blockIdx.x * blockDim.x + threadIdx.x;
    if (i >= n4) return;
    float4 v = ((const float4*)x)[i];
    ((__half2*)xh)[i * 2]     = __floats2half2_rn(v.x, v.y);
    ((__half2*)xh)[i * 2 + 1] = __floats2half2_rn(v.z, v.w);
}

// both weights: W [K][256] fp32 -> Wt [256][K] fp16 (batched in one launch)
__global__ void convert_wt_both_k(const float* __restrict__ W1, __half* __restrict__ W1t,
                                  const float* __restrict__ W2, __half* __restrict__ W2t)
{
    int idx = blockIdx.x * blockDim.x + threadIdx.x;
    if (idx < 128 * 256) {
        int k = idx >> 8, n = idx & 255;
        W1t[n * 128 + k] = __float2half(W1[idx]);
    }
    if (idx < 256 * 256) {
        int k = idx >> 8, n = idx & 255;
        W2t[n * 256 + k] = __float2half(W2[idx]);
    }
}

// ---------------- CSR build (by destination) ----------------
__global__ void zero_deg_k(int* deg, int n) {
    int i = blockIdx.x * blockDim.x + threadIdx.x;
    if (i < n) deg[i] = 0;
}

__global__ void count_k(const int* __restrict__ ei, int E, int N, int* __restrict__ deg) {
    int i = blockIdx.x * blockDim.x + threadIdx.x;
    if (i >= E) return;
    int d = ei[E + i];
    if ((unsigned)d < (unsigned)N) atomicAdd(&deg[d], 1);
}

__global__ __launch_bounds__(1024) void scan_k(
    const int* __restrict__ deg, int* __restrict__ row_ptr,
    int* __restrict__ cursor, int N)
{
    __shared__ int part[1024];
    int t = threadIdx.x;
    int chunk = (N + 1023) / 1024;
    int b = t * chunk, e = min(b + chunk, N);
    int sum = 0;
    for (int i = b; i < e; i++) sum += deg[i];
    part[t] = sum;
    __syncthreads();
    for (int off = 1; off < 1024; off <<= 1) {
        int v = (t >= off) ? part[t - off] : 0;
        __syncthreads();
        part[t] += v;
        __syncthreads();
    }
    int run = (t > 0) ? part[t - 1] : 0;
    for (int i = b; i < e; i++) {
        row_ptr[i] = run;
        cursor[i] = run;
        run += deg[i];
    }
    if (t == 1023) row_ptr[N] = part[1023];
}

__global__ void scatter_k(const int* __restrict__ ei, int E, int N,
                          int* __restrict__ cursor, int* __restrict__ csr_src)
{
    int i = blockIdx.x * blockDim.x + threadIdx.x;
    if (i >= E) return;
    int s = ei[i];
    int d = ei[E + i];
    if ((unsigned)s >= (unsigned)N || (unsigned)d >= (unsigned)N) return;
    int pos = atomicAdd(&cursor[d], 1);
    csr_src[pos] = s;
}

// ================= fp16 tensor-core GEMM + fused attention scores ==========
// C[M,256] = A[M,K] @ Bt[256,K]^T stored fp16; K multiple of 32.
// Epilogue combines per-(row,head) attention partials in smem, plain stores
// (no atomics, no pre-zero). A/C/asrc/adst may be row-offset by the caller.
#define GBM 128
#define GBN 128
#define GBK 32
#define HSTR 40                              // halfs per smem row (bank-conflict-free)
#define STAGE_H (2 * GBM * HSTR)             // halfs per stage = 10240
#define GEMM_SMEM_BYTES (2 * STAGE_H * 2)    // 40960 bytes

__device__ __forceinline__ void gemm_load_tiles(
    __half* As, __half* Bs, const __half* __restrict__ A, const __half* __restrict__ Bt,
    int M, int K, int block_row, int block_col, int k0, int tid)
{
#pragma unroll
    for (int i = 0; i < 2; i++) {
        int idx = tid * 2 + i;            // 0..511
        int r   = idx >> 2;               // 0..127
        int c   = (idx & 3) * 8;          // 0,8,16,24 (halfs)
        int gr = block_row + r;
        if (gr >= M) gr = M - 1;          // clamp: rows >= M never stored
        cp16(&As[r * HSTR + c], &A[(size_t)gr * K + k0 + c]);
    }
#pragma unroll
    for (int i = 0; i < 2; i++) {
        int idx = tid * 2 + i;
        int r   = idx >> 2;
        int c   = (idx & 3) * 8;
        cp16(&Bs[r * HSTR + c], &Bt[(size_t)(block_col + r) * K + k0 + c]);
    }
    cp_commit();
}

__global__ __launch_bounds__(256) void gemm_f16(
    const __half* __restrict__ A, const __half* __restrict__ Bt,
    __half* __restrict__ C, int M, int K,
    const float* __restrict__ att_s, const float* __restrict__ att_d,
    float* __restrict__ asrc, float* __restrict__ adst)
{
    extern __shared__ __half smem[];
    __shared__ float satt_s[GBN], satt_d[GBN];
    __shared__ float2 sred[4][GBM];   // [warp_n][row] -> (s_partial, d_partial)
    const int tid  = threadIdx.x;
    const int lane = tid & 31;
    const int wid  = tid >> 5;
    const int warp_m = wid & 1;
    const int warp_n = wid >> 1;
    const int gid = lane >> 2;
    const int tig = lane & 3;
    const int block_row = blockIdx.y * GBM;
    const int block_col = blockIdx.x * GBN;

    if (tid < GBN) {
        satt_s[tid] = att_s[block_col + tid];
        satt_d[tid] = att_d[block_col + tid];
    }

    float4 acc[4][4];
#pragma unroll
    for (int i = 0; i < 4; i++)
#pragma unroll
        for (int j = 0; j < 4; j++) acc[i][j] = make_float4(0.f, 0.f, 0.f, 0.f);

    const int niter = K / GBK;
    gemm_load_tiles(smem, smem + GBM * HSTR, A, Bt, M, K, block_row, block_col, 0, tid);

    for (int it = 0; it < niter; it++) {
        int cur = it & 1;
        if (it + 1 < niter) {
            __half* As_n = smem + (1 - cur) * STAGE_H;
            gemm_load_tiles(As_n, As_n + GBM * HSTR, A, Bt, M, K, block_row, block_col,
                            (it + 1) * GBK, tid);
            cp_wait<1>();
        } else {
            cp_wait<0>();
        }
        __syncthreads();

        const __half* As = smem + cur * STAGE_H;
        const __half* Bs = As + GBM * HSTR;

#pragma unroll
        for (int ks = 0; ks < 2; ks++) {        // two k16 steps per GBK=32
            int kb = ks * 16;
            uint32_t af[4][4], bf[4][2];
#pragma unroll
            for (int tm = 0; tm < 4; tm++) {
                int row = warp_m * 64 + tm * 16 + gid;
                const __half* ap = &As[row * HSTR + kb + 2 * tig];
                af[tm][0] = *(const uint32_t*)ap;
                af[tm][1] = *(const uint32_t*)(ap + 8 * HSTR);
                af[tm][2] = *(const uint32_t*)(ap + 8);
                af[tm][3] = *(const uint32_t*)(ap + 8 * HSTR + 8);
            }
#pragma unroll
            for (int tn = 0; tn < 4; tn++) {
                int col = warp_n * 32 + tn * 8 + gid;
                const __half* bp = &Bs[col * HSTR + kb + 2 * tig];
                bf[tn][0] = *(const uint32_t*)bp;
                bf[tn][1] = *(const uint32_t*)(bp + 8);
            }
#pragma unroll
            for (int tm = 0; tm < 4; tm++)
#pragma unroll
                for (int tn = 0; tn < 4; tn++)
                    mma_f16(acc[tm][tn], af[tm][0], af[tm][1], af[tm][2], af[tm][3],
                            bf[tn][0], bf[tn][1]);
        }
        __syncthreads();
    }

    // epilogue: store C (fp16) + per-(row,head) attention partials via smem
#pragma unroll
    for (int tm = 0; tm < 4; tm++) {
        int r0 = warp_m * 64 + tm * 16 + gid;   // local row; +8 for second
        int grow0 = block_row + r0;
        int grow1 = grow0 + 8;
        float s0 = 0.f, s1 = 0.f, d0 = 0.f, d1 = 0.f;
#pragma unroll
        for (int tn = 0; tn < 4; tn++) {
            int lc = warp_n * 32 + tn * 8 + tig * 2;
            float ws0 = satt_s[lc], ws1 = satt_s[lc + 1];
            float wd0 = satt_d[lc], wd1 = satt_d[lc + 1];
            float4 a = acc[tm][tn];
            s0 += ws0 * a.x + ws1 * a.y;
            d0 += wd0 * a.x + wd1 * a.y;
            s1 += ws0 * a.z + ws1 * a.w;
            d1 += wd0 * a.z + wd1 * a.w;
            int gcol = block_col + lc;
            if (grow0 < M)
                *(__half2*)&C[(size_t)grow0 * HCn + gcol] = __floats2half2_rn(a.x, a.y);
            if (grow1 < M)
                *(__half2*)&C[(size_t)grow1 * HCn + gcol] = __floats2half2_rn(a.z, a.w);
        }
#pragma unroll
        for (int o = 1; o <= 2; o <<= 1) {
            s0 += __shfl_xor_sync(0xffffffffu, s0, o);
            s1 += __shfl_xor_sync(0xffffffffu, s1, o);
            d0 += __shfl_xor_sync(0xffffffffu, d0, o);
            d1 += __shfl_xor_sync(0xffffffffu, d1, o);
        }
        if (tig == 0) {
            sred[warp_n][r0]     = make_float2(s0, d0);
            sred[warp_n][r0 + 8] = make_float2(s1, d1);
        }
    }
    __syncthreads();
    {
        int r  = tid >> 1;          // 0..127
        int hl = tid & 1;           // head within this block's 2 heads
        float2 p0 = sred[2 * hl][r];
        float2 p1 = sred[2 * hl + 1][r];
        int grow = block_row + r;
        if (grow < M) {
            int hb = block_col >> 6;     // 0 or 2
            asrc[grow * Hh + hb + hl] = p0.x + p1.x;
            adst[grow * Hh + hb + hl] = p0.y + p1.y;
        }
    }
}

// ======== fused CSR aggregation + softmax + bias + ELU (fp16 gather) ========
// one warp per destination node in [n0, n1); depth-3 pipeline (round-9 proven).
template <bool CONCAT>
__global__ __launch_bounds__(256) void gat_agg_csr(
    const int* __restrict__ row_ptr, const int* __restrict__ csr_src,
    const float* __restrict__ asrc, const float* __restrict__ adst,
    const __half* __restrict__ h, const float* __restrict__ bias,
    __half* __restrict__ outh, float* __restrict__ outf, int n0, int n1)
{
    __shared__ float sb[HCn];
    int tid = threadIdx.x;
    if (tid < (CONCAT ? HCn : Cc)) sb[tid] = bias[tid];
    __syncthreads();

    int d = n0 + blockIdx.x * 8 + (tid >> 5);
    int lane = tid & 31;
    if (d >= n1) return;
    int head = lane >> 3;

    float adst_h = adst[d * Hh + head];
    int beg = row_ptr[d], end = row_ptr[d + 1];

    float4 acc0 = make_float4(0.f, 0.f, 0.f, 0.f);
    float4 acc1 = make_float4(0.f, 0.f, 0.f, 0.f);
    float dsum = 0.f;

    int   sA = (beg < end) ? csr_src[beg] : d;
    float aA = asrc[sA * Hh + head];
    uint4 rA = *(const uint4*)&h[(size_t)sA * HCn + lane * 8];
    int   sB = (beg + 1 < end) ? csr_src[beg + 1] : d;
    float aB = asrc[sB * Hh + head];
    uint4 rB = *(const uint4*)&h[(size_t)sB * HCn + lane * 8];
    int   sC = (beg + 2 < end) ? csr_src[beg + 2] : d;
    float aC = asrc[sC * Hh + head];
    uint4 rC = *(const uint4*)&h[(size_t)sC * HCn + lane * 8];

    for (int k = beg; k <= end; k++) {           // k == end -> self loop
        int   sN = (k + 3 < end) ? csr_src[k + 3] : d;
        float aN = asrc[sN * Hh + head];
        uint4 rN = *(const uint4*)&h[(size_t)sN * HCn + lane * 8];

        float p = __expf(lrelu(aA + adst_h));
        dsum += p;
        const __half2* hh = (const __half2*)&rA;
        float2 f0 = __half22float2(hh[0]);
        float2 f1 = __half22float2(hh[1]);
        float2 f2 = __half22float2(hh[2]);
        float2 f3 = __half22float2(hh[3]);
        acc0.x += p * f0.x; acc0.y += p * f0.y; acc0.z += p * f1.x; acc0.w += p * f1.y;
        acc1.x += p * f2.x; acc1.y += p * f2.y; acc1.z += p * f3.x; acc1.w += p * f3.y;

        sA = sB; aA = aB; rA = rB;
        sB = sC; aB = aC; rB = rC;
        sC = sN; aC = aN; rC = rN;
    }

    float inv = 1.f / dsum;

    if (CONCAT) {
        int c = lane * 8;
        struct { __half2 a, b, c2, d2; } pk;
        pk.a  = __floats2half2_rn(elu1(acc0.x * inv + sb[c + 0]),
                                  elu1(acc0.y * inv + sb[c + 1]));
        pk.b  = __floats2half2_rn(elu1(acc0.z * inv + sb[c + 2]),
                                  elu1(acc0.w * inv + sb[c + 3]));
        pk.c2 = __floats2half2_rn(elu1(acc1.x * inv + sb[c + 4]),
                                  elu1(acc1.y * inv + sb[c + 5]));
        pk.d2 = __floats2half2_rn(elu1(acc1.z * inv + sb[c + 6]),
                                  elu1(acc1.w * inv + sb[c + 7]));
        *(uint4*)&outh[(size_t)d * HCn + c] = *(uint4*)&pk;
    } else {
        float v[8];
        v[0] = acc0.x * inv; v[1] = acc0.y * inv; v[2] = acc0.z * inv; v[3] = acc0.w * inv;
        v[4] = acc1.x * inv; v[5] = acc1.y * inv; v[6] = acc1.z * inv; v[7] = acc1.w * inv;
#pragma unroll
        for (int j = 0; j < 8; j++) {
            v[j] += __shfl_xor_sync(0xffffffffu, v[j], 8);
            v[j] += __shfl_xor_sync(0xffffffffu, v[j], 16);
        }
        if (lane < 8) {
            int c = lane * 8;
            float4 o0, o1;
            o0.x = elu1(v[0] * 0.25f + sb[c + 0]);
            o0.y = elu1(v[1] * 0.25f + sb[c + 1]);
            o0.z = elu1(v[2] * 0.25f + sb[c + 2]);
            o0.w = elu1(v[3] * 0.25f + sb[c + 3]);
            o1.x = elu1(v[4] * 0.25f + sb[c + 4]);
            o1.y = elu1(v[5] * 0.25f + sb[c + 5]);
            o1.z = elu1(v[6] * 0.25f + sb[c + 6]);
            o1.w = elu1(v[7] * 0.25f + sb[c + 7]);
            float4* op = (float4*)&outf[(size_t)d * Cc + c];
            op[0] = o0;
            op[1] = o1;
        }
    }
}

// ---------------- pooling ----------------
__global__ void graph_bounds_k(const int* __restrict__ batch, int N,
                               int* __restrict__ start, int* __restrict__ end)
{
    int n = blockIdx.x * blockDim.x + threadIdx.x;
    if (n >= N) return;
    int g = batch[n];
    if (g < 0 || g >= NG) return;
    atomicMin(&start[g], n);
    atomicMax(&end[g], n + 1);
}

__global__ __launch_bounds__(256) void pool_k(
    const float* __restrict__ hf, const int* __restrict__ start,
    const int* __restrict__ end, float* __restrict__ pooled)
{
    int g = blockIdx.x;
    int tid = threadIdx.x;
    int col = tid & 63, sub = tid >> 6;
    int s = start[g], e = end[g];
    if (s > e) { s = 0; e = 0; }
    float acc = 0.f;
    for (int n = s + sub; n < e; n += 4) acc += hf[(size_t)n * Cc + col];
    __shared__ float sm[256];
    sm[tid] = acc;
    __syncthreads();
    if (sub == 0) {
        float v = sm[col] + sm[64 + col] + sm[128 + col] + sm[192 + col];
        float cnt = (e > s) ? (float)(e - s) : 0.f;
        pooled[g * Cc + col] = v / fmaxf(cnt, 1.0f);
    }
}

// ---------------- final head ----------------
__global__ __launch_bounds__(1024) void head_k(
    const float* __restrict__ pooled, const float* __restrict__ Wa,
    const float* __restrict__ ba, float* __restrict__ out)
{
    __shared__ float sW[Cc * NA];
    int t = threadIdx.y * 32 + threadIdx.x;
    for (int i = t; i < Cc * NA; i += 1024) sW[i] = Wa[i];
    __syncthreads();
    int a = threadIdx.x;
#pragma unroll
    for (int rep = 0; rep < 2; rep++) {
        int g = threadIdx.y + rep * 32;
        float acc = ba[a];
#pragma unroll 8
        for (int c = 0; c < Cc; c++) acc = fmaf(pooled[g * Cc + c], sW[c * NA + a], acc);
        out[g * NA + a] = acc;
    }
}

// ---------------- host orchestration ----------------
static void* symp(const void* sym) {
    void* p = nullptr;
    cudaGetSymbolAddress(&p, sym);
    return p;
}

extern "C" void kernel_launch(void* const* d_in, const int* in_sizes, int n_in,
                              void* d_out, int out_size)
{
    // one-time host-side setup (first call is the uncaptured correctness run)
    static cudaStream_t sB = nullptr;
    static cudaEvent_t evFork = nullptr, evJoin = nullptr;
    static cudaEvent_t evA0 = nullptr, evA1 = nullptr, evG2 = nullptr;
    if (!sB) {
        cudaStreamCreateWithFlags(&sB, cudaStreamNonBlocking);
        cudaEventCreateWithFlags(&evFork, cudaEventDisableTiming);
        cudaEventCreateWithFlags(&evJoin, cudaEventDisableTiming);
        cudaEventCreateWithFlags(&evA0, cudaEventDisableTiming);
        cudaEventCreateWithFlags(&evA1, cudaEventDisableTiming);
        cudaEventCreateWithFlags(&evG2, cudaEventDisableTiming);
    }

    // -------- robust input mapping (filter size-1 scalar inputs) --------
    const void* t[13];
    int tsz[13];
    int cnt = 0;
    for (int i = 0; i < n_in && cnt < 13; i++) {
        if (in_sizes[i] <= 1) continue;
        t[cnt] = d_in[i];
        tsz[cnt] = in_sizes[i];
        cnt++;
    }
    if (cnt < 13) return;

    const float* x     = (const float*)t[0];
    const int*   ei    = (const int*)t[1];
    const int*   batch = (const int*)t[2];
    const float* W1    = (const float*)t[3];
    const float* attS1 = (const float*)t[4];
    const float* attD1 = (const float*)t[5];
    const float* b1    = (const float*)t[6];
    const float* W2    = (const float*)t[7];
    const float* attS2 = (const float*)t[8];
    const float* attD2 = (const float*)t[9];
    const float* b2    = (const float*)t[10];
    const float* Wa    = (const float*)t[11];
    const float* ba    = (const float*)t[12];

    const int Fin = 128;
    int N = tsz[0] / Fin;
    int E = tsz[1] / 2;
    if (N > MAXN || E > MAXE || N <= 0 || E <= 0) return;

    __half* ah  = (__half*)symp(g_ah);
    __half* h   = (__half*)symp(g_h);
    __half* w1t = (__half*)symp(g_w1t);
    __half* w2t = (__half*)symp(g_w2t);
    float* asrc = (float*)symp(g_asrc);
    float* adst = (float*)symp(g_adst);
    float* hf   = (float*)symp(g_hf);
    float* pooled = (float*)symp(g_pooled);
    int* gstart = (int*)symp(g_start);
    int* gend   = (int*)symp(g_end);
    int* rowptr = (int*)symp(g_rowptr);
    int* cursor = (int*)symp(g_cursor);
    int* csr    = (int*)symp(g_csr);

    // row split point (multiple of GBM)
    int Nh = ((N / 2 + GBM - 1) / GBM) * GBM;
    if (Nh > N) Nh = N;
    int Nrem = N - Nh;

    // ======== fork: side stream builds CSR + pooling prep ========
    cudaEventRecord(evFork, 0);
    cudaStreamWaitEvent(sB, evFork, 0);

    zero_deg_k<<<(N + 255) / 256, 256, 0, sB>>>(cursor, N);
    count_k<<<(E + 255) / 256, 256, 0, sB>>>(ei, E, N, cursor);
    scan_k<<<1, 1024, 0, sB>>>(cursor, rowptr, cursor, N);
    scatter_k<<<(E + 255) / 256, 256, 0, sB>>>(ei, E, N, cursor, csr);
    init_bounds_k<<<(NG * Cc + 255) / 256, 256, 0, sB>>>(gstart, gend, pooled);
    graph_bounds_k<<<(N + 255) / 256, 256, 0, sB>>>(batch, N, gstart, gend);
    cudaEventRecord(evJoin, sB);

    // ======== main stream: converts + layer-1 GEMM ========
    size_t n4 = (size_t)N * Fin / 4;
    convert_x_k<<<(unsigned)((n4 + 255) / 256), 256>>>(x, ah, n4);
    convert_wt_both_k<<<(256 * 256 + 255) / 256, 256>>>(W1, w1t, W2, w2t);
    gemm_f16<<<dim3(2, (N + GBM - 1) / GBM), 256, GEMM_SMEM_BYTES>>>(
        ah, w1t, h, N, Fin, attS1, attD1, asrc, adst);

    // join: aggregation needs the CSR
    cudaStreamWaitEvent(0, evJoin, 0);

    // ---- agg1 in two halves; gemm2 per half runs on sB as halves complete ----
    gat_agg_csr<true><<<(unsigned)((Nh + 7) / 8), 256>>>(
        rowptr, csr, asrc, adst, h, b1, ah, nullptr, 0, Nh);
    cudaEventRecord(evA0, 0);
    if (Nrem > 0) {
        gat_agg_csr<true><<<(unsigned)((Nrem + 7) / 8), 256>>>(
            rowptr, csr, asrc, adst, h, b1, ah, nullptr, Nh, N);
    }
    cudaEventRecord(evA1, 0);

    cudaStreamWaitEvent(sB, evA0, 0);
    gemm_f16<<<dim3(2, Nh / GBM), 256, GEMM_SMEM_BYTES, sB>>>(
        ah, w2t, h, Nh, HCn, attS2, attD2, asrc, adst);
    if (Nrem > 0) {
        cudaStreamWaitEvent(sB, evA1, 0);
        gemm_f16<<<dim3(2, (Nrem + GBM - 1) / GBM), 256, GEMM_SMEM_BYTES, sB>>>(
            ah + (size_t)Nh * HCn, w2t, h + (size_t)Nh * HCn, Nrem, HCn,
            attS2, attD2, asrc + Nh * Hh, adst + Nh * Hh);
    }
    cudaEventRecord(evG2, sB);

    // ---- layer-2 aggregation (needs all of h + scores) ----
    cudaStreamWaitEvent(0, evG2, 0);
    gat_agg_csr<false><<<(unsigned)((N + 7) / 8), 256>>>(
        rowptr, csr, asrc, adst, h, b2, nullptr, hf, 0, N);

    // ---- pooling + head ----
    pool_k<<<NG, 256>>>(hf, gstart, gend, pooled);
    head_k<<<1, dim3(32, 32)>>>(pooled, Wa, ba, (float*)d_out);
}

// round 13
// speedup vs baseline: 1.0172x; 1.0172x over previous
#include <cuda_runtime.h>
#include <cuda_fp16.h>
#include <math.h>
#include <stdio.h>
#include <stdint.h>

// ---------------- static problem capacities ----------------
#define MAXN 50000
#define MAXE 800000
#define HCn  256      // H*C
#define Hh   4
#define Cc   64
#define NG   64       // graphs
#define NA   32       // actions

// ---------------- device scratch (allocation-free rule) ----------------
__device__ __half g_ah[(size_t)MAXN * HCn];   // GEMM A input: x fp16, then h2 fp16
__device__ __half g_h [(size_t)MAXN * HCn];   // GEMM output (gather source)
__device__ __half g_w1t[256 * 128];           // W1^T fp16  [n][k]
__device__ __half g_w2t[256 * 256];           // W2^T fp16  [n][k]
__device__ float g_asrc[MAXN * Hh];
__device__ float g_adst[MAXN * Hh];
__device__ float g_hf  [(size_t)MAXN * Cc];   // final node features [N,64]
__device__ float g_pooled[NG * Cc];
__device__ int   g_start[NG];
__device__ int   g_end  [NG];
__device__ int   g_rowptr[MAXN + 1];
__device__ int   g_cursor[MAXN];
__device__ int   g_csr[MAXE];

// ---------------- helpers ----------------
__device__ __forceinline__ float lrelu(float x) { return fmaxf(x, 0.2f * x); }
__device__ __forceinline__ float elu1(float x)  { return x > 0.f ? x : expm1f(x); }

__device__ __forceinline__ void mma_f16(float4& c,
    uint32_t a0, uint32_t a1, uint32_t a2, uint32_t a3,
    uint32_t b0, uint32_t b1)
{
    asm volatile(
        "mma.sync.aligned.m16n8k16.row.col.f32.f16.f16.f32 "
        "{%0,%1,%2,%3}, {%4,%5,%6,%7}, {%8,%9}, {%0,%1,%2,%3};"
        : "+f"(c.x), "+f"(c.y), "+f"(c.z), "+f"(c.w)
        : "r"(a0), "r"(a1), "r"(a2), "r"(a3), "r"(b0), "r"(b1));
}

__device__ __forceinline__ void cp16(void* sm, const void* gm) {
    uint32_t sa = (uint32_t)__cvta_generic_to_shared(sm);
    asm volatile("cp.async.ca.shared.global [%0], [%1], 16;" :: "r"(sa), "l"(gm));
}
__device__ __forceinline__ void cp_commit() {
    asm volatile("cp.async.commit_group;" ::: "memory");
}
template <int Npend>
__device__ __forceinline__ void cp_wait() {
    asm volatile("cp.async.wait_group %0;" :: "n"(Npend) : "memory");
}

// ---------------- small utility kernels ----------------
__global__ void init_bounds_k(int* start, int* end, float* pooled) {
    int i = blockIdx.x * blockDim.x + threadIdx.x;
    if (i < NG) { start[i] = 1 << 30; end[i] = 0; }
    if (i < NG * Cc) pooled[i] = 0.f;
}

// x (fp32) -> fp16, vectorized 4-wide
__global__ void convert_x_k(const float* __restrict__ x, __half* __restrict__ xh, size_t n4) {
    size_t i = (size_t)blockIdx.x * blockDim.x + threadIdx.x;
    if (i >= n4) return;
    float4 v = ((const float4*)x)[i];
    ((__half2*)xh)[i * 2]     = __floats2half2_rn(v.x, v.y);
    ((__half2*)xh)[i * 2 + 1] = __floats2half2_rn(v.z, v.w);
}

// both weights: W [K][256] fp32 -> Wt [256][K] fp16 (batched in one launch)
__global__ void convert_wt_both_k(const float* __restrict__ W1, __half* __restrict__ W1t,
                                  const float* __restrict__ W2, __half* __restrict__ W2t)
{
    int idx = blockIdx.x * blockDim.x + threadIdx.x;
    if (idx < 128 * 256) {
        int k = idx >> 8, n = idx & 255;
        W1t[n * 128 + k] = __float2half(W1[idx]);
    }
    if (idx < 256 * 256) {
        int k = idx >> 8, n = idx & 255;
        W2t[n * 256 + k] = __float2half(W2[idx]);
    }
}

// ---------------- CSR build (by destination) ----------------
__global__ void zero_deg_k(int* deg, int n) {
    int i = blockIdx.x * blockDim.x + threadIdx.x;
    if (i < n) deg[i] = 0;
}

__global__ void count_k(const int* __restrict__ ei, int E, int N, int* __restrict__ deg) {
    int i = blockIdx.x * blockDim.x + threadIdx.x;
    if (i >= E) return;
    int d = ei[E + i];
    if ((unsigned)d < (unsigned)N) atomicAdd(&deg[d], 1);
}

__global__ __launch_bounds__(1024) void scan_k(
    const int* __restrict__ deg, int* __restrict__ row_ptr,
    int* __restrict__ cursor, int N)
{
    __shared__ int part[1024];
    int t = threadIdx.x;
    int chunk = (N + 1023) / 1024;
    int b = t * chunk, e = min(b + chunk, N);
    int sum = 0;
    for (int i = b; i < e; i++) sum += deg[i];
    part[t] = sum;
    __syncthreads();
    for (int off = 1; off < 1024; off <<= 1) {
        int v = (t >= off) ? part[t - off] : 0;
        __syncthreads();
        part[t] += v;
        __syncthreads();
    }
    int run = (t > 0) ? part[t - 1] : 0;
    for (int i = b; i < e; i++) {
        row_ptr[i] = run;
        cursor[i] = run;
        run += deg[i];
    }
    if (t == 1023) row_ptr[N] = part[1023];
}

__global__ void scatter_k(const int* __restrict__ ei, int E, int N,
                          int* __restrict__ cursor, int* __restrict__ csr_src)
{
    int i = blockIdx.x * blockDim.x + threadIdx.x;
    if (i >= E) return;
    int s = ei[i];
    int d = ei[E + i];
    if ((unsigned)s >= (unsigned)N || (unsigned)d >= (unsigned)N) return;
    int pos = atomicAdd(&cursor[d], 1);
    csr_src[pos] = s;
}

// ================= fp16 tensor-core GEMM + fused attention scores ==========
// C[M,256] = A[M,K] @ Bt[256,K]^T stored fp16; K multiple of 32.
// Epilogue combines per-(row,head) attention partials in smem, plain stores
// (no atomics, no pre-zero needed).
#define GBM 128
#define GBN 128
#define GBK 32
#define HSTR 40                              // halfs per smem row (bank-conflict-free)
#define STAGE_H (2 * GBM * HSTR)             // halfs per stage = 10240
#define GEMM_SMEM_BYTES (2 * STAGE_H * 2)    // 40960 bytes

__device__ __forceinline__ void gemm_load_tiles(
    __half* As, __half* Bs, const __half* __restrict__ A, const __half* __restrict__ Bt,
    int M, int K, int block_row, int block_col, int k0, int tid)
{
#pragma unroll
    for (int i = 0; i < 2; i++) {
        int idx = tid * 2 + i;            // 0..511
        int r   = idx >> 2;               // 0..127
        int c   = (idx & 3) * 8;          // 0,8,16,24 (halfs)
        int gr = block_row + r;
        if (gr >= M) gr = M - 1;          // clamp: rows >= M never stored
        cp16(&As[r * HSTR + c], &A[(size_t)gr * K + k0 + c]);
    }
#pragma unroll
    for (int i = 0; i < 2; i++) {
        int idx = tid * 2 + i;
        int r   = idx >> 2;
        int c   = (idx & 3) * 8;
        cp16(&Bs[r * HSTR + c], &Bt[(size_t)(block_col + r) * K + k0 + c]);
    }
    cp_commit();
}

__global__ __launch_bounds__(256) void gemm_f16(
    const __half* __restrict__ A, const __half* __restrict__ Bt,
    __half* __restrict__ C, int M, int K,
    const float* __restrict__ att_s, const float* __restrict__ att_d,
    float* __restrict__ asrc, float* __restrict__ adst)
{
    extern __shared__ __half smem[];
    __shared__ float satt_s[GBN], satt_d[GBN];
    __shared__ float2 sred[4][GBM];   // [warp_n][row] -> (s_partial, d_partial)
    const int tid  = threadIdx.x;
    const int lane = tid & 31;
    const int wid  = tid >> 5;
    const int warp_m = wid & 1;
    const int warp_n = wid >> 1;
    const int gid = lane >> 2;
    const int tig = lane & 3;
    const int block_row = blockIdx.y * GBM;
    const int block_col = blockIdx.x * GBN;

    if (tid < GBN) {
        satt_s[tid] = att_s[block_col + tid];
        satt_d[tid] = att_d[block_col + tid];
    }

    float4 acc[4][4];
#pragma unroll
    for (int i = 0; i < 4; i++)
#pragma unroll
        for (int j = 0; j < 4; j++) acc[i][j] = make_float4(0.f, 0.f, 0.f, 0.f);

    const int niter = K / GBK;
    gemm_load_tiles(smem, smem + GBM * HSTR, A, Bt, M, K, block_row, block_col, 0, tid);

    for (int it = 0; it < niter; it++) {
        int cur = it & 1;
        if (it + 1 < niter) {
            __half* As_n = smem + (1 - cur) * STAGE_H;
            gemm_load_tiles(As_n, As_n + GBM * HSTR, A, Bt, M, K, block_row, block_col,
                            (it + 1) * GBK, tid);
            cp_wait<1>();
        } else {
            cp_wait<0>();
        }
        __syncthreads();

        const __half* As = smem + cur * STAGE_H;
        const __half* Bs = As + GBM * HSTR;

#pragma unroll
        for (int ks = 0; ks < 2; ks++) {        // two k16 steps per GBK=32
            int kb = ks * 16;
            uint32_t af[4][4], bf[4][2];
#pragma unroll
            for (int tm = 0; tm < 4; tm++) {
                int row = warp_m * 64 + tm * 16 + gid;
                const __half* ap = &As[row * HSTR + kb + 2 * tig];
                af[tm][0] = *(const uint32_t*)ap;
                af[tm][1] = *(const uint32_t*)(ap + 8 * HSTR);
                af[tm][2] = *(const uint32_t*)(ap + 8);
                af[tm][3] = *(const uint32_t*)(ap + 8 * HSTR + 8);
            }
#pragma unroll
            for (int tn = 0; tn < 4; tn++) {
                int col = warp_n * 32 + tn * 8 + gid;
                const __half* bp = &Bs[col * HSTR + kb + 2 * tig];
                bf[tn][0] = *(const uint32_t*)bp;
                bf[tn][1] = *(const uint32_t*)(bp + 8);
            }
#pragma unroll
            for (int tm = 0; tm < 4; tm++)
#pragma unroll
                for (int tn = 0; tn < 4; tn++)
                    mma_f16(acc[tm][tn], af[tm][0], af[tm][1], af[tm][2], af[tm][3],
                            bf[tn][0], bf[tn][1]);
        }
        __syncthreads();
    }

    // epilogue: store C (fp16) + per-(row,head) attention partials via smem
#pragma unroll
    for (int tm = 0; tm < 4; tm++) {
        int r0 = warp_m * 64 + tm * 16 + gid;   // local row; +8 for second
        int grow0 = block_row + r0;
        int grow1 = grow0 + 8;
        float s0 = 0.f, s1 = 0.f, d0 = 0.f, d1 = 0.f;
#pragma unroll
        for (int tn = 0; tn < 4; tn++) {
            int lc = warp_n * 32 + tn * 8 + tig * 2;
            float ws0 = satt_s[lc], ws1 = satt_s[lc + 1];
            float wd0 = satt_d[lc], wd1 = satt_d[lc + 1];
            float4 a = acc[tm][tn];
            s0 += ws0 * a.x + ws1 * a.y;
            d0 += wd0 * a.x + wd1 * a.y;
            s1 += ws0 * a.z + ws1 * a.w;
            d1 += wd0 * a.z + wd1 * a.w;
            int gcol = block_col + lc;
            if (grow0 < M)
                *(__half2*)&C[(size_t)grow0 * HCn + gcol] = __floats2half2_rn(a.x, a.y);
            if (grow1 < M)
                *(__half2*)&C[(size_t)grow1 * HCn + gcol] = __floats2half2_rn(a.z, a.w);
        }
#pragma unroll
        for (int o = 1; o <= 2; o <<= 1) {
            s0 += __shfl_xor_sync(0xffffffffu, s0, o);
            s1 += __shfl_xor_sync(0xffffffffu, s1, o);
            d0 += __shfl_xor_sync(0xffffffffu, d0, o);
            d1 += __shfl_xor_sync(0xffffffffu, d1, o);
        }
        if (tig == 0) {
            sred[warp_n][r0]     = make_float2(s0, d0);
            sred[warp_n][r0 + 8] = make_float2(s1, d1);
        }
    }
    __syncthreads();
    {
        int r  = tid >> 1;          // 0..127
        int hl = tid & 1;           // head within this block's 2 heads
        float2 p0 = sred[2 * hl][r];
        float2 p1 = sred[2 * hl + 1][r];
        int grow = block_row + r;
        if (grow < M) {
            int hb = block_col >> 6;     // 0 or 2
            asrc[grow * Hh + hb + hl] = p0.x + p1.x;
            adst[grow * Hh + hb + hl] = p0.y + p1.y;
        }
    }
}

// ======== fused CSR aggregation + softmax + bias + ELU (fp16 gather) ========
// one warp per destination node; depth-3 pipeline (round-9/11 proven).
template <bool CONCAT>
__global__ __launch_bounds__(256) void gat_agg_csr(
    const int* __restrict__ row_ptr, const int* __restrict__ csr_src,
    const float* __restrict__ asrc, const float* __restrict__ adst,
    const __half* __restrict__ h, const float* __restrict__ bias,
    __half* __restrict__ outh, float* __restrict__ outf, int N)
{
    __shared__ float sb[HCn];
    int tid = threadIdx.x;
    if (tid < (CONCAT ? HCn : Cc)) sb[tid] = bias[tid];
    __syncthreads();

    int d = blockIdx.x * 8 + (tid >> 5);
    int lane = tid & 31;
    if (d >= N) return;
    int head = lane >> 3;

    float adst_h = adst[d * Hh + head];
    int beg = row_ptr[d], end = row_ptr[d + 1];

    float4 acc0 = make_float4(0.f, 0.f, 0.f, 0.f);
    float4 acc1 = make_float4(0.f, 0.f, 0.f, 0.f);
    float dsum = 0.f;

    int   sA = (beg < end) ? csr_src[beg] : d;
    float aA = asrc[sA * Hh + head];
    uint4 rA = *(const uint4*)&h[(size_t)sA * HCn + lane * 8];
    int   sB = (beg + 1 < end) ? csr_src[beg + 1] : d;
    float aB = asrc[sB * Hh + head];
    uint4 rB = *(const uint4*)&h[(size_t)sB * HCn + lane * 8];
    int   sC = (beg + 2 < end) ? csr_src[beg + 2] : d;
    float aC = asrc[sC * Hh + head];
    uint4 rC = *(const uint4*)&h[(size_t)sC * HCn + lane * 8];

    for (int k = beg; k <= end; k++) {           // k == end -> self loop
        int   sN = (k + 3 < end) ? csr_src[k + 3] : d;
        float aN = asrc[sN * Hh + head];
        uint4 rN = *(const uint4*)&h[(size_t)sN * HCn + lane * 8];

        float p = __expf(lrelu(aA + adst_h));
        dsum += p;
        const __half2* hh = (const __half2*)&rA;
        float2 f0 = __half22float2(hh[0]);
        float2 f1 = __half22float2(hh[1]);
        float2 f2 = __half22float2(hh[2]);
        float2 f3 = __half22float2(hh[3]);
        acc0.x += p * f0.x; acc0.y += p * f0.y; acc0.z += p * f1.x; acc0.w += p * f1.y;
        acc1.x += p * f2.x; acc1.y += p * f2.y; acc1.z += p * f3.x; acc1.w += p * f3.y;

        sA = sB; aA = aB; rA = rB;
        sB = sC; aB = aC; rB = rC;
        sC = sN; aC = aN; rC = rN;
    }

    float inv = 1.f / dsum;

    if (CONCAT) {
        int c = lane * 8;
        struct { __half2 a, b, c2, d2; } pk;
        pk.a  = __floats2half2_rn(elu1(acc0.x * inv + sb[c + 0]),
                                  elu1(acc0.y * inv + sb[c + 1]));
        pk.b  = __floats2half2_rn(elu1(acc0.z * inv + sb[c + 2]),
                                  elu1(acc0.w * inv + sb[c + 3]));
        pk.c2 = __floats2half2_rn(elu1(acc1.x * inv + sb[c + 4]),
                                  elu1(acc1.y * inv + sb[c + 5]));
        pk.d2 = __floats2half2_rn(elu1(acc1.z * inv + sb[c + 6]),
                                  elu1(acc1.w * inv + sb[c + 7]));
        *(uint4*)&outh[(size_t)d * HCn + c] = *(uint4*)&pk;
    } else {
        float v[8];
        v[0] = acc0.x * inv; v[1] = acc0.y * inv; v[2] = acc0.z * inv; v[3] = acc0.w * inv;
        v[4] = acc1.x * inv; v[5] = acc1.y * inv; v[6] = acc1.z * inv; v[7] = acc1.w * inv;
#pragma unroll
        for (int j = 0; j < 8; j++) {
            v[j] += __shfl_xor_sync(0xffffffffu, v[j], 8);
            v[j] += __shfl_xor_sync(0xffffffffu, v[j], 16);
        }
        if (lane < 8) {
            int c = lane * 8;
            float4 o0, o1;
            o0.x = elu1(v[0] * 0.25f + sb[c + 0]);
            o0.y = elu1(v[1] * 0.25f + sb[c + 1]);
            o0.z = elu1(v[2] * 0.25f + sb[c + 2]);
            o0.w = elu1(v[3] * 0.25f + sb[c + 3]);
            o1.x = elu1(v[4] * 0.25f + sb[c + 4]);
            o1.y = elu1(v[5] * 0.25f + sb[c + 5]);
            o1.z = elu1(v[6] * 0.25f + sb[c + 6]);
            o1.w = elu1(v[7] * 0.25f + sb[c + 7]);
            float4* op = (float4*)&outf[(size_t)d * Cc + c];
            op[0] = o0;
            op[1] = o1;
        }
    }
}

// ---------------- pooling ----------------
__global__ void graph_bounds_k(const int* __restrict__ batch, int N,
                               int* __restrict__ start, int* __restrict__ end)
{
    int n = blockIdx.x * blockDim.x + threadIdx.x;
    if (n >= N) return;
    int g = batch[n];
    if (g < 0 || g >= NG) return;
    atomicMin(&start[g], n);
    atomicMax(&end[g], n + 1);
}

__global__ __launch_bounds__(256) void pool_k(
    const float* __restrict__ hf, const int* __restrict__ start,
    const int* __restrict__ end, float* __restrict__ pooled)
{
    int g = blockIdx.x;
    int tid = threadIdx.x;
    int col = tid & 63, sub = tid >> 6;
    int s = start[g], e = end[g];
    if (s > e) { s = 0; e = 0; }
    float acc = 0.f;
    for (int n = s + sub; n < e; n += 4) acc += hf[(size_t)n * Cc + col];
    __shared__ float sm[256];
    sm[tid] = acc;
    __syncthreads();
    if (sub == 0) {
        float v = sm[col] + sm[64 + col] + sm[128 + col] + sm[192 + col];
        float cnt = (e > s) ? (float)(e - s) : 0.f;
        pooled[g * Cc + col] = v / fmaxf(cnt, 1.0f);
    }
}

// ---------------- final head ----------------
__global__ __launch_bounds__(1024) void head_k(
    const float* __restrict__ pooled, const float* __restrict__ Wa,
    const float* __restrict__ ba, float* __restrict__ out)
{
    __shared__ float sW[Cc * NA];
    int t = threadIdx.y * 32 + threadIdx.x;
    for (int i = t; i < Cc * NA; i += 1024) sW[i] = Wa[i];
    __syncthreads();
    int a = threadIdx.x;
#pragma unroll
    for (int rep = 0; rep < 2; rep++) {
        int g = threadIdx.y + rep * 32;
        float acc = ba[a];
#pragma unroll 8
        for (int c = 0; c < Cc; c++) acc = fmaf(pooled[g * Cc + c], sW[c * NA + a], acc);
        out[g * NA + a] = acc;
    }
}

// ---------------- host orchestration ----------------
static void* symp(const void* sym) {
    void* p = nullptr;
    cudaGetSymbolAddress(&p, sym);
    return p;
}

extern "C" void kernel_launch(void* const* d_in, const int* in_sizes, int n_in,
                              void* d_out, int out_size)
{
    // one-time host-side setup (first call is the uncaptured correctness run)
    static cudaStream_t sB = nullptr;
    static cudaEvent_t evFork = nullptr, evJoin = nullptr;
    if (!sB) {
        cudaStreamCreateWithFlags(&sB, cudaStreamNonBlocking);
        cudaEventCreateWithFlags(&evFork, cudaEventDisableTiming);
        cudaEventCreateWithFlags(&evJoin, cudaEventDisableTiming);
    }

    // -------- robust input mapping (filter size-1 scalar inputs) --------
    const void* t[13];
    int tsz[13];
    int cnt = 0;
    for (int i = 0; i < n_in && cnt < 13; i++) {
        if (in_sizes[i] <= 1) continue;
        t[cnt] = d_in[i];
        tsz[cnt] = in_sizes[i];
        cnt++;
    }
    if (cnt < 13) return;

    const float* x     = (const float*)t[0];
    const int*   ei    = (const int*)t[1];
    const int*   batch = (const int*)t[2];
    const float* W1    = (const float*)t[3];
    const float* attS1 = (const float*)t[4];
    const float* attD1 = (const float*)t[5];
    const float* b1    = (const float*)t[6];
    const float* W2    = (const float*)t[7];
    const float* attS2 = (const float*)t[8];
    const float* attD2 = (const float*)t[9];
    const float* b2    = (const float*)t[10];
    const float* Wa    = (const float*)t[11];
    const float* ba    = (const float*)t[12];

    const int Fin = 128;
    int N = tsz[0] / Fin;
    int E = tsz[1] / 2;
    if (N > MAXN || E > MAXE || N <= 0 || E <= 0) return;

    __half* ah  = (__half*)symp(g_ah);
    __half* h   = (__half*)symp(g_h);
    __half* w1t = (__half*)symp(g_w1t);
    __half* w2t = (__half*)symp(g_w2t);
    float* asrc = (float*)symp(g_asrc);
    float* adst = (float*)symp(g_adst);
    float* hf   = (float*)symp(g_hf);
    float* pooled = (float*)symp(g_pooled);
    int* gstart = (int*)symp(g_start);
    int* gend   = (int*)symp(g_end);
    int* rowptr = (int*)symp(g_rowptr);
    int* cursor = (int*)symp(g_cursor);
    int* csr    = (int*)symp(g_csr);

    dim3 gemm_grid(HCn / GBN, (N + GBM - 1) / GBM);
    unsigned agg_grid = (unsigned)((N + 7) / 8);

    // ======== fork: side stream builds CSR + pooling prep ========
    cudaEventRecord(evFork, 0);
    cudaStreamWaitEvent(sB, evFork, 0);

    zero_deg_k<<<(N + 255) / 256, 256, 0, sB>>>(cursor, N);
    count_k<<<(E + 255) / 256, 256, 0, sB>>>(ei, E, N, cursor);
    scan_k<<<1, 1024, 0, sB>>>(cursor, rowptr, cursor, N);
    scatter_k<<<(E + 255) / 256, 256, 0, sB>>>(ei, E, N, cursor, csr);
    init_bounds_k<<<(NG * Cc + 255) / 256, 256, 0, sB>>>(gstart, gend, pooled);
    graph_bounds_k<<<(N + 255) / 256, 256, 0, sB>>>(batch, N, gstart, gend);
    cudaEventRecord(evJoin, sB);

    // ======== main stream: converts + layer-1 GEMM ========
    size_t n4 = (size_t)N * Fin / 4;
    convert_x_k<<<(unsigned)((n4 + 255) / 256), 256>>>(x, ah, n4);
    convert_wt_both_k<<<(256 * 256 + 255) / 256, 256>>>(W1, w1t, W2, w2t);
    gemm_f16<<<gemm_grid, 256, GEMM_SMEM_BYTES>>>(ah, w1t, h, N, Fin,
                                                  attS1, attD1, asrc, adst);

    // join: aggregation needs the CSR
    cudaStreamWaitEvent(0, evJoin, 0);
    gat_agg_csr<true><<<agg_grid, 256>>>(rowptr, csr, asrc, adst, h, b1, ah, nullptr, N);

    // ---- layer 2 ----
    gemm_f16<<<gemm_grid, 256, GEMM_SMEM_BYTES>>>(ah, w2t, h, N, HCn,
                                                  attS2, attD2, asrc, adst);
    gat_agg_csr<false><<<agg_grid, 256>>>(rowptr, csr, asrc, adst, h, b2, nullptr, hf, N);

    // ---- pooling + head ----
    pool_k<<<NG, 256>>>(hf, gstart, gend, pooled);
    head_k<<<1, dim3(32, 32)>>>(pooled, Wa, ba, (float*)d_out);
}

// round 14
// speedup vs baseline: 1.0234x; 1.0061x over previous
#include <cuda_runtime.h>
#include <cuda_fp16.h>
#include <math.h>
#include <stdio.h>
#include <stdint.h>

// ---------------- static problem capacities ----------------
#define MAXN 50000
#define MAXE 800000
#define HCn  256      // H*C
#define Hh   4
#define Cc   64
#define NG   64       // graphs
#define NA   32       // actions

// ---------------- device scratch (allocation-free rule) ----------------
__device__ __half g_ah[(size_t)MAXN * HCn];   // layer-2 GEMM A input (agg1 output, fp16)
__device__ __half g_h [(size_t)MAXN * HCn];   // GEMM output (gather source)
__device__ __half g_w1t[256 * 128];           // W1^T fp16  [n][k]
__device__ __half g_w2t[256 * 256];           // W2^T fp16  [n][k]
__device__ float g_asrc[MAXN * Hh];
__device__ float g_adst[MAXN * Hh];
__device__ float g_hf  [(size_t)MAXN * Cc];   // final node features [N,64]
__device__ float g_pooled[NG * Cc];
__device__ int   g_start[NG];
__device__ int   g_end  [NG];
__device__ int   g_rowptr[MAXN + 1];
__device__ int   g_cursor[MAXN];
__device__ int   g_csr[MAXE];

// ---------------- helpers ----------------
__device__ __forceinline__ float lrelu(float x) { return fmaxf(x, 0.2f * x); }
__device__ __forceinline__ float elu1(float x)  { return x > 0.f ? x : expm1f(x); }

__device__ __forceinline__ void mma_f16(float4& c,
    uint32_t a0, uint32_t a1, uint32_t a2, uint32_t a3,
    uint32_t b0, uint32_t b1)
{
    asm volatile(
        "mma.sync.aligned.m16n8k16.row.col.f32.f16.f16.f32 "
        "{%0,%1,%2,%3}, {%4,%5,%6,%7}, {%8,%9}, {%0,%1,%2,%3};"
        : "+f"(c.x), "+f"(c.y), "+f"(c.z), "+f"(c.w)
        : "r"(a0), "r"(a1), "r"(a2), "r"(a3), "r"(b0), "r"(b1));
}

__device__ __forceinline__ void cp16(void* sm, const void* gm) {
    uint32_t sa = (uint32_t)__cvta_generic_to_shared(sm);
    asm volatile("cp.async.ca.shared.global [%0], [%1], 16;" :: "r"(sa), "l"(gm));
}
__device__ __forceinline__ void cp_commit() {
    asm volatile("cp.async.commit_group;" ::: "memory");
}
template <int Npend>
__device__ __forceinline__ void cp_wait() {
    asm volatile("cp.async.wait_group %0;" :: "n"(Npend) : "memory");
}

__device__ __forceinline__ uint32_t f2h2(float lo, float hi) {
    __half2 h = __floats2half2_rn(lo, hi);
    return *(uint32_t*)&h;
}

// ---------------- small utility kernels ----------------
__global__ void init_bounds_k(int* start, int* end, float* pooled) {
    int i = blockIdx.x * blockDim.x + threadIdx.x;
    if (i < NG) { start[i] = 1 << 30; end[i] = 0; }
    if (i < NG * Cc) pooled[i] = 0.f;
}

// both weights: W [K][256] fp32 -> Wt [256][K] fp16 (batched in one launch)
__global__ void convert_wt_both_k(const float* __restrict__ W1, __half* __restrict__ W1t,
                                  const float* __restrict__ W2, __half* __restrict__ W2t)
{
    int idx = blockIdx.x * blockDim.x + threadIdx.x;
    if (idx < 128 * 256) {
        int k = idx >> 8, n = idx & 255;
        W1t[n * 128 + k] = __float2half(W1[idx]);
    }
    if (idx < 256 * 256) {
        int k = idx >> 8, n = idx & 255;
        W2t[n * 256 + k] = __float2half(W2[idx]);
    }
}

// ---------------- CSR build (by destination) ----------------
__global__ void zero_deg_k(int* deg, int n) {
    int i = blockIdx.x * blockDim.x + threadIdx.x;
    if (i < n) deg[i] = 0;
}

__global__ void count_k(const int* __restrict__ ei, int E, int N, int* __restrict__ deg) {
    int i = blockIdx.x * blockDim.x + threadIdx.x;
    if (i >= E) return;
    int d = ei[E + i];
    if ((unsigned)d < (unsigned)N) atomicAdd(&deg[d], 1);
}

__global__ __launch_bounds__(1024) void scan_k(
    const int* __restrict__ deg, int* __restrict__ row_ptr,
    int* __restrict__ cursor, int N)
{
    __shared__ int part[1024];
    int t = threadIdx.x;
    int chunk = (N + 1023) / 1024;
    int b = t * chunk, e = min(b + chunk, N);
    int sum = 0;
    for (int i = b; i < e; i++) sum += deg[i];
    part[t] = sum;
    __syncthreads();
    for (int off = 1; off < 1024; off <<= 1) {
        int v = (t >= off) ? part[t - off] : 0;
        __syncthreads();
        part[t] += v;
        __syncthreads();
    }
    int run = (t > 0) ? part[t - 1] : 0;
    for (int i = b; i < e; i++) {
        row_ptr[i] = run;
        cursor[i] = run;
        run += deg[i];
    }
    if (t == 1023) row_ptr[N] = part[1023];
}

__global__ void scatter_k(const int* __restrict__ ei, int E, int N,
                          int* __restrict__ cursor, int* __restrict__ csr_src)
{
    int i = blockIdx.x * blockDim.x + threadIdx.x;
    if (i >= E) return;
    int s = ei[i];
    int d = ei[E + i];
    if ((unsigned)s >= (unsigned)N || (unsigned)d >= (unsigned)N) return;
    int pos = atomicAdd(&cursor[d], 1);
    csr_src[pos] = s;
}

// ================= tensor-core GEMM + fused attention scores ==========
// C[M,256] = A[M,K] @ Bt[256,K]^T; C fp16. Two A-dtype variants:
//   gemm_f16 : A fp16 (layer 2)
//   gemm_f32a: A fp32 (layer 1, reads x directly; fragments converted rn)
// Epilogue combines per-(row,head) attention partials in smem, plain stores.
#define GBM 128
#define GBN 128
#define GBK 32
#define HSTR 40                              // halfs per smem row
#define FSTR 36                              // floats per smem row (f32 A variant)
#define STAGE_H (2 * GBM * HSTR)             // halfs per stage = 10240
#define GEMM_SMEM_BYTES (2 * STAGE_H * 2)    // 40960 bytes
#define STAGE32_BYTES (GBM * FSTR * 4 + GBM * HSTR * 2)   // 18432 + 10240 = 28672
#define GEMM32_SMEM_BYTES (2 * STAGE32_BYTES)             // 57344 bytes

// ---- shared epilogue ----
__device__ __forceinline__ void gemm_epilogue(
    float4 (&acc)[4][4], const float* satt_s, const float* satt_d,
    float2 (*sred)[GBM],
    __half* __restrict__ C, int M,
    float* __restrict__ asrc, float* __restrict__ adst,
    int block_row, int block_col,
    int tid, int warp_m, int warp_n, int gid, int tig)
{
#pragma unroll
    for (int tm = 0; tm < 4; tm++) {
        int r0 = warp_m * 64 + tm * 16 + gid;
        int grow0 = block_row + r0;
        int grow1 = grow0 + 8;
        float s0 = 0.f, s1 = 0.f, d0 = 0.f, d1 = 0.f;
#pragma unroll
        for (int tn = 0; tn < 4; tn++) {
            int lc = warp_n * 32 + tn * 8 + tig * 2;
            float ws0 = satt_s[lc], ws1 = satt_s[lc + 1];
            float wd0 = satt_d[lc], wd1 = satt_d[lc + 1];
            float4 a = acc[tm][tn];
            s0 += ws0 * a.x + ws1 * a.y;
            d0 += wd0 * a.x + wd1 * a.y;
            s1 += ws0 * a.z + ws1 * a.w;
            d1 += wd0 * a.z + wd1 * a.w;
            int gcol = block_col + lc;
            if (grow0 < M)
                *(__half2*)&C[(size_t)grow0 * HCn + gcol] = __floats2half2_rn(a.x, a.y);
            if (grow1 < M)
                *(__half2*)&C[(size_t)grow1 * HCn + gcol] = __floats2half2_rn(a.z, a.w);
        }
#pragma unroll
        for (int o = 1; o <= 2; o <<= 1) {
            s0 += __shfl_xor_sync(0xffffffffu, s0, o);
            s1 += __shfl_xor_sync(0xffffffffu, s1, o);
            d0 += __shfl_xor_sync(0xffffffffu, d0, o);
            d1 += __shfl_xor_sync(0xffffffffu, d1, o);
        }
        if (tig == 0) {
            sred[warp_n][r0]     = make_float2(s0, d0);
            sred[warp_n][r0 + 8] = make_float2(s1, d1);
        }
    }
    __syncthreads();
    {
        int r  = tid >> 1;
        int hl = tid & 1;
        float2 p0 = sred[2 * hl][r];
        float2 p1 = sred[2 * hl + 1][r];
        int grow = block_row + r;
        if (grow < M) {
            int hb = block_col >> 6;
            asrc[grow * Hh + hb + hl] = p0.x + p1.x;
            adst[grow * Hh + hb + hl] = p0.y + p1.y;
        }
    }
}

// ---- fp16-A variant (layer 2) ----
__device__ __forceinline__ void load_tiles_f16(
    __half* As, __half* Bs, const __half* __restrict__ A, const __half* __restrict__ Bt,
    int M, int K, int block_row, int block_col, int k0, int tid)
{
#pragma unroll
    for (int i = 0; i < 2; i++) {
        int idx = tid * 2 + i;
        int r   = idx >> 2;
        int c   = (idx & 3) * 8;
        int gr = block_row + r;
        if (gr >= M) gr = M - 1;
        cp16(&As[r * HSTR + c], &A[(size_t)gr * K + k0 + c]);
    }
#pragma unroll
    for (int i = 0; i < 2; i++) {
        int idx = tid * 2 + i;
        int r   = idx >> 2;
        int c   = (idx & 3) * 8;
        cp16(&Bs[r * HSTR + c], &Bt[(size_t)(block_col + r) * K + k0 + c]);
    }
    cp_commit();
}

__global__ __launch_bounds__(256) void gemm_f16(
    const __half* __restrict__ A, const __half* __restrict__ Bt,
    __half* __restrict__ C, int M, int K,
    const float* __restrict__ att_s, const float* __restrict__ att_d,
    float* __restrict__ asrc, float* __restrict__ adst)
{
    extern __shared__ __half smem[];
    __shared__ float satt_s[GBN], satt_d[GBN];
    __shared__ float2 sred[4][GBM];
    const int tid  = threadIdx.x;
    const int lane = tid & 31;
    const int wid  = tid >> 5;
    const int warp_m = wid & 1;
    const int warp_n = wid >> 1;
    const int gid = lane >> 2;
    const int tig = lane & 3;
    const int block_row = blockIdx.y * GBM;
    const int block_col = blockIdx.x * GBN;

    if (tid < GBN) {
        satt_s[tid] = att_s[block_col + tid];
        satt_d[tid] = att_d[block_col + tid];
    }

    float4 acc[4][4];
#pragma unroll
    for (int i = 0; i < 4; i++)
#pragma unroll
        for (int j = 0; j < 4; j++) acc[i][j] = make_float4(0.f, 0.f, 0.f, 0.f);

    const int niter = K / GBK;
    load_tiles_f16(smem, smem + GBM * HSTR, A, Bt, M, K, block_row, block_col, 0, tid);

    for (int it = 0; it < niter; it++) {
        int cur = it & 1;
        if (it + 1 < niter) {
            __half* As_n = smem + (1 - cur) * STAGE_H;
            load_tiles_f16(As_n, As_n + GBM * HSTR, A, Bt, M, K, block_row, block_col,
                           (it + 1) * GBK, tid);
            cp_wait<1>();
        } else {
            cp_wait<0>();
        }
        __syncthreads();

        const __half* As = smem + cur * STAGE_H;
        const __half* Bs = As + GBM * HSTR;

#pragma unroll
        for (int ks = 0; ks < 2; ks++) {
            int kb = ks * 16;
            uint32_t af[4][4], bf[4][2];
#pragma unroll
            for (int tm = 0; tm < 4; tm++) {
                int row = warp_m * 64 + tm * 16 + gid;
                const __half* ap = &As[row * HSTR + kb + 2 * tig];
                af[tm][0] = *(const uint32_t*)ap;
                af[tm][1] = *(const uint32_t*)(ap + 8 * HSTR);
                af[tm][2] = *(const uint32_t*)(ap + 8);
                af[tm][3] = *(const uint32_t*)(ap + 8 * HSTR + 8);
            }
#pragma unroll
            for (int tn = 0; tn < 4; tn++) {
                int col = warp_n * 32 + tn * 8 + gid;
                const __half* bp = &Bs[col * HSTR + kb + 2 * tig];
                bf[tn][0] = *(const uint32_t*)bp;
                bf[tn][1] = *(const uint32_t*)(bp + 8);
            }
#pragma unroll
            for (int tm = 0; tm < 4; tm++)
#pragma unroll
                for (int tn = 0; tn < 4; tn++)
                    mma_f16(acc[tm][tn], af[tm][0], af[tm][1], af[tm][2], af[tm][3],
                            bf[tn][0], bf[tn][1]);
        }
        __syncthreads();
    }

    gemm_epilogue(acc, satt_s, satt_d, sred, C, M, asrc, adst,
                  block_row, block_col, tid, warp_m, warp_n, gid, tig);
}

// ---- fp32-A variant (layer 1: A = x directly) ----
__device__ __forceinline__ void load_tiles_f32a(
    float* Asf, __half* Bs, const float* __restrict__ A, const __half* __restrict__ Bt,
    int M, int K, int block_row, int block_col, int k0, int tid)
{
    // A tile: 128 rows x 32 floats = 1024 float4; 4 per thread
    int r0 = tid >> 3;             // 0..31
    int f4 = (tid & 7) * 4;        // 0..28
#pragma unroll
    for (int i = 0; i < 4; i++) {
        int r = r0 + i * 32;
        int gr = block_row + r;
        if (gr >= M) gr = M - 1;
        cp16(&Asf[r * FSTR + f4], &A[(size_t)gr * K + k0 + f4]);
    }
    // B tile: 128 rows x 32 halfs = 512 16B chunks; 2 per thread
#pragma unroll
    for (int i = 0; i < 2; i++) {
        int idx = tid * 2 + i;
        int r   = idx >> 2;
        int c   = (idx & 3) * 8;
        cp16(&Bs[r * HSTR + c], &Bt[(size_t)(block_col + r) * K + k0 + c]);
    }
    cp_commit();
}

__global__ __launch_bounds__(256) void gemm_f32a(
    const float* __restrict__ A, const __half* __restrict__ Bt,
    __half* __restrict__ C, int M, int K,
    const float* __restrict__ att_s, const float* __restrict__ att_d,
    float* __restrict__ asrc, float* __restrict__ adst)
{
    extern __shared__ char smem8[];
    __shared__ float satt_s[GBN], satt_d[GBN];
    __shared__ float2 sred[4][GBM];
    const int tid  = threadIdx.x;
    const int lane = tid & 31;
    const int wid  = tid >> 5;
    const int warp_m = wid & 1;
    const int warp_n = wid >> 1;
    const int gid = lane >> 2;
    const int tig = lane & 3;
    const int block_row = blockIdx.y * GBM;
    const int block_col = blockIdx.x * GBN;

    if (tid < GBN) {
        satt_s[tid] = att_s[block_col + tid];
        satt_d[tid] = att_d[block_col + tid];
    }

    float4 acc[4][4];
#pragma unroll
    for (int i = 0; i < 4; i++)
#pragma unroll
        for (int j = 0; j < 4; j++) acc[i][j] = make_float4(0.f, 0.f, 0.f, 0.f);

    const int niter = K / GBK;
    {
        float* As0 = (float*)smem8;
        __half* Bs0 = (__half*)(smem8 + GBM * FSTR * 4);
        load_tiles_f32a(As0, Bs0, A, Bt, M, K, block_row, block_col, 0, tid);
    }

    for (int it = 0; it < niter; it++) {
        int cur = it & 1;
        if (it + 1 < niter) {
            char* base_n = smem8 + (1 - cur) * STAGE32_BYTES;
            load_tiles_f32a((float*)base_n, (__half*)(base_n + GBM * FSTR * 4),
                            A, Bt, M, K, block_row, block_col, (it + 1) * GBK, tid);
            cp_wait<1>();
        } else {
            cp_wait<0>();
        }
        __syncthreads();

        const char* base = smem8 + cur * STAGE32_BYTES;
        const float* As = (const float*)base;
        const __half* Bs = (const __half*)(base + GBM * FSTR * 4);

#pragma unroll
        for (int ks = 0; ks < 2; ks++) {
            int kb = ks * 16;
            uint32_t af[4][4], bf[4][2];
#pragma unroll
            for (int tm = 0; tm < 4; tm++) {
                int row = warp_m * 64 + tm * 16 + gid;
                const float* ap = &As[row * FSTR + kb + 2 * tig];
                af[tm][0] = f2h2(ap[0], ap[1]);
                af[tm][1] = f2h2(ap[8 * FSTR], ap[8 * FSTR + 1]);
                af[tm][2] = f2h2(ap[8], ap[9]);
                af[tm][3] = f2h2(ap[8 * FSTR + 8], ap[8 * FSTR + 9]);
            }
#pragma unroll
            for (int tn = 0; tn < 4; tn++) {
                int col = warp_n * 32 + tn * 8 + gid;
                const __half* bp = &Bs[col * HSTR + kb + 2 * tig];
                bf[tn][0] = *(const uint32_t*)bp;
                bf[tn][1] = *(const uint32_t*)(bp + 8);
            }
#pragma unroll
            for (int tm = 0; tm < 4; tm++)
#pragma unroll
                for (int tn = 0; tn < 4; tn++)
                    mma_f16(acc[tm][tn], af[tm][0], af[tm][1], af[tm][2], af[tm][3],
                            bf[tn][0], bf[tn][1]);
        }
        __syncthreads();
    }

    gemm_epilogue(acc, satt_s, satt_d, sred, C, M, asrc, adst,
                  block_row, block_col, tid, warp_m, warp_n, gid, tig);
}

// ======== fused CSR aggregation + softmax + bias + ELU (fp16 gather) ========
// one warp per destination node; depth-3 pipeline (round-9/11 proven).
template <bool CONCAT>
__global__ __launch_bounds__(256) void gat_agg_csr(
    const int* __restrict__ row_ptr, const int* __restrict__ csr_src,
    const float* __restrict__ asrc, const float* __restrict__ adst,
    const __half* __restrict__ h, const float* __restrict__ bias,
    __half* __restrict__ outh, float* __restrict__ outf, int N)
{
    __shared__ float sb[HCn];
    int tid = threadIdx.x;
    if (tid < (CONCAT ? HCn : Cc)) sb[tid] = bias[tid];
    __syncthreads();

    int d = blockIdx.x * 8 + (tid >> 5);
    int lane = tid & 31;
    if (d >= N) return;
    int head = lane >> 3;

    float adst_h = adst[d * Hh + head];
    int beg = row_ptr[d], end = row_ptr[d + 1];

    float4 acc0 = make_float4(0.f, 0.f, 0.f, 0.f);
    float4 acc1 = make_float4(0.f, 0.f, 0.f, 0.f);
    float dsum = 0.f;

    int   sA = (beg < end) ? csr_src[beg] : d;
    float aA = asrc[sA * Hh + head];
    uint4 rA = *(const uint4*)&h[(size_t)sA * HCn + lane * 8];
    int   sB = (beg + 1 < end) ? csr_src[beg + 1] : d;
    float aB = asrc[sB * Hh + head];
    uint4 rB = *(const uint4*)&h[(size_t)sB * HCn + lane * 8];
    int   sC = (beg + 2 < end) ? csr_src[beg + 2] : d;
    float aC = asrc[sC * Hh + head];
    uint4 rC = *(const uint4*)&h[(size_t)sC * HCn + lane * 8];

    for (int k = beg; k <= end; k++) {           // k == end -> self loop
        int   sN = (k + 3 < end) ? csr_src[k + 3] : d;
        float aN = asrc[sN * Hh + head];
        uint4 rN = *(const uint4*)&h[(size_t)sN * HCn + lane * 8];

        float p = __expf(lrelu(aA + adst_h));
        dsum += p;
        const __half2* hh = (const __half2*)&rA;
        float2 f0 = __half22float2(hh[0]);
        float2 f1 = __half22float2(hh[1]);
        float2 f2 = __half22float2(hh[2]);
        float2 f3 = __half22float2(hh[3]);
        acc0.x += p * f0.x; acc0.y += p * f0.y; acc0.z += p * f1.x; acc0.w += p * f1.y;
        acc1.x += p * f2.x; acc1.y += p * f2.y; acc1.z += p * f3.x; acc1.w += p * f3.y;

        sA = sB; aA = aB; rA = rB;
        sB = sC; aB = aC; rB = rC;
        sC = sN; aC = aN; rC = rN;
    }

    float inv = 1.f / dsum;

    if (CONCAT) {
        int c = lane * 8;
        struct { __half2 a, b, c2, d2; } pk;
        pk.a  = __floats2half2_rn(elu1(acc0.x * inv + sb[c + 0]),
                                  elu1(acc0.y * inv + sb[c + 1]));
        pk.b  = __floats2half2_rn(elu1(acc0.z * inv + sb[c + 2]),
                                  elu1(acc0.w * inv + sb[c + 3]));
        pk.c2 = __floats2half2_rn(elu1(acc1.x * inv + sb[c + 4]),
                                  elu1(acc1.y * inv + sb[c + 5]));
        pk.d2 = __floats2half2_rn(elu1(acc1.z * inv + sb[c + 6]),
                                  elu1(acc1.w * inv + sb[c + 7]));
        *(uint4*)&outh[(size_t)d * HCn + c] = *(uint4*)&pk;
    } else {
        float v[8];
        v[0] = acc0.x * inv; v[1] = acc0.y * inv; v[2] = acc0.z * inv; v[3] = acc0.w * inv;
        v[4] = acc1.x * inv; v[5] = acc1.y * inv; v[6] = acc1.z * inv; v[7] = acc1.w * inv;
#pragma unroll
        for (int j = 0; j < 8; j++) {
            v[j] += __shfl_xor_sync(0xffffffffu, v[j], 8);
            v[j] += __shfl_xor_sync(0xffffffffu, v[j], 16);
        }
        if (lane < 8) {
            int c = lane * 8;
            float4 o0, o1;
            o0.x = elu1(v[0] * 0.25f + sb[c + 0]);
            o0.y = elu1(v[1] * 0.25f + sb[c + 1]);
            o0.z = elu1(v[2] * 0.25f + sb[c + 2]);
            o0.w = elu1(v[3] * 0.25f + sb[c + 3]);
            o1.x = elu1(v[4] * 0.25f + sb[c + 4]);
            o1.y = elu1(v[5] * 0.25f + sb[c + 5]);
            o1.z = elu1(v[6] * 0.25f + sb[c + 6]);
            o1.w = elu1(v[7] * 0.25f + sb[c + 7]);
            float4* op = (float4*)&outf[(size_t)d * Cc + c];
            op[0] = o0;
            op[1] = o1;
        }
    }
}

// ---------------- pooling ----------------
__global__ void graph_bounds_k(const int* __restrict__ batch, int N,
                               int* __restrict__ start, int* __restrict__ end)
{
    int n = blockIdx.x * blockDim.x + threadIdx.x;
    if (n >= N) return;
    int g = batch[n];
    if (g < 0 || g >= NG) return;
    atomicMin(&start[g], n);
    atomicMax(&end[g], n + 1);
}

__global__ __launch_bounds__(256) void pool_k(
    const float* __restrict__ hf, const int* __restrict__ start,
    const int* __restrict__ end, float* __restrict__ pooled)
{
    int g = blockIdx.x;
    int tid = threadIdx.x;
    int col = tid & 63, sub = tid >> 6;
    int s = start[g], e = end[g];
    if (s > e) { s = 0; e = 0; }
    float acc = 0.f;
    for (int n = s + sub; n < e; n += 4) acc += hf[(size_t)n * Cc + col];
    __shared__ float sm[256];
    sm[tid] = acc;
    __syncthreads();
    if (sub == 0) {
        float v = sm[col] + sm[64 + col] + sm[128 + col] + sm[192 + col];
        float cnt = (e > s) ? (float)(e - s) : 0.f;
        pooled[g * Cc + col] = v / fmaxf(cnt, 1.0f);
    }
}

// ---------------- final head ----------------
__global__ __launch_bounds__(1024) void head_k(
    const float* __restrict__ pooled, const float* __restrict__ Wa,
    const float* __restrict__ ba, float* __restrict__ out)
{
    __shared__ float sW[Cc * NA];
    int t = threadIdx.y * 32 + threadIdx.x;
    for (int i = t; i < Cc * NA; i += 1024) sW[i] = Wa[i];
    __syncthreads();
    int a = threadIdx.x;
#pragma unroll
    for (int rep = 0; rep < 2; rep++) {
        int g = threadIdx.y + rep * 32;
        float acc = ba[a];
#pragma unroll 8
        for (int c = 0; c < Cc; c++) acc = fmaf(pooled[g * Cc + c], sW[c * NA + a], acc);
        out[g * NA + a] = acc;
    }
}

// ---------------- host orchestration ----------------
static void* symp(const void* sym) {
    void* p = nullptr;
    cudaGetSymbolAddress(&p, sym);
    return p;
}

extern "C" void kernel_launch(void* const* d_in, const int* in_sizes, int n_in,
                              void* d_out, int out_size)
{
    // one-time host-side setup (first call is the uncaptured correctness run)
    static cudaStream_t sB = nullptr;
    static cudaEvent_t evFork = nullptr, evJoin = nullptr;
    if (!sB) {
        cudaStreamCreateWithFlags(&sB, cudaStreamNonBlocking);
        cudaEventCreateWithFlags(&evFork, cudaEventDisableTiming);
        cudaEventCreateWithFlags(&evJoin, cudaEventDisableTiming);
        cudaFuncSetAttribute(gemm_f32a, cudaFuncAttributeMaxDynamicSharedMemorySize,
                             GEMM32_SMEM_BYTES);
    }

    // -------- robust input mapping (filter size-1 scalar inputs) --------
    const void* t[13];
    int tsz[13];
    int cnt = 0;
    for (int i = 0; i < n_in && cnt < 13; i++) {
        if (in_sizes[i] <= 1) continue;
        t[cnt] = d_in[i];
        tsz[cnt] = in_sizes[i];
        cnt++;
    }
    if (cnt < 13) return;

    const float* x     = (const float*)t[0];
    const int*   ei    = (const int*)t[1];
    const int*   batch = (const int*)t[2];
    const float* W1    = (const float*)t[3];
    const float* attS1 = (const float*)t[4];
    const float* attD1 = (const float*)t[5];
    const float* b1    = (const float*)t[6];
    const float* W2    = (const float*)t[7];
    const float* attS2 = (const float*)t[8];
    const float* attD2 = (const float*)t[9];
    const float* b2    = (const float*)t[10];
    const float* Wa    = (const float*)t[11];
    const float* ba    = (const float*)t[12];

    const int Fin = 128;
    int N = tsz[0] / Fin;
    int E = tsz[1] / 2;
    if (N > MAXN || E > MAXE || N <= 0 || E <= 0) return;

    __half* ah  = (__half*)symp(g_ah);
    __half* h   = (__half*)symp(g_h);
    __half* w1t = (__half*)symp(g_w1t);
    __half* w2t = (__half*)symp(g_w2t);
    float* asrc = (float*)symp(g_asrc);
    float* adst = (float*)symp(g_adst);
    float* hf   = (float*)symp(g_hf);
    float* pooled = (float*)symp(g_pooled);
    int* gstart = (int*)symp(g_start);
    int* gend   = (int*)symp(g_end);
    int* rowptr = (int*)symp(g_rowptr);
    int* cursor = (int*)symp(g_cursor);
    int* csr    = (int*)symp(g_csr);

    dim3 gemm_grid(HCn / GBN, (N + GBM - 1) / GBM);
    unsigned agg_grid = (unsigned)((N + 7) / 8);

    // ======== fork: side stream builds CSR + pooling prep ========
    cudaEventRecord(evFork, 0);
    cudaStreamWaitEvent(sB, evFork, 0);

    zero_deg_k<<<(N + 255) / 256, 256, 0, sB>>>(cursor, N);
    count_k<<<(E + 255) / 256, 256, 0, sB>>>(ei, E, N, cursor);
    scan_k<<<1, 1024, 0, sB>>>(cursor, rowptr, cursor, N);
    scatter_k<<<(E + 255) / 256, 256, 0, sB>>>(ei, E, N, cursor, csr);
    init_bounds_k<<<(NG * Cc + 255) / 256, 256, 0, sB>>>(gstart, gend, pooled);
    graph_bounds_k<<<(N + 255) / 256, 256, 0, sB>>>(batch, N, gstart, gend);
    cudaEventRecord(evJoin, sB);

    // ======== main stream: weight convert + layer-1 GEMM (reads x fp32) ========
    convert_wt_both_k<<<(256 * 256 + 255) / 256, 256>>>(W1, w1t, W2, w2t);
    gemm_f32a<<<gemm_grid, 256, GEMM32_SMEM_BYTES>>>(x, w1t, h, N, Fin,
                                                     attS1, attD1, asrc, adst);

    // join: aggregation needs the CSR
    cudaStreamWaitEvent(0, evJoin, 0);
    gat_agg_csr<true><<<agg_grid, 256>>>(rowptr, csr, asrc, adst, h, b1, ah, nullptr, N);

    // ---- layer 2 ----
    gemm_f16<<<gemm_grid, 256, GEMM_SMEM_BYTES>>>(ah, w2t, h, N, HCn,
                                                  attS2, attD2, asrc, adst);
    gat_agg_csr<false><<<agg_grid, 256>>>(rowptr, csr, asrc, adst, h, b2, nullptr, hf, N);

    // ---- pooling + head ----
    pool_k<<<NG, 256>>>(hf, gstart, gend, pooled);
    head_k<<<1, dim3(32, 32)>>>(pooled, Wa, ba, (float*)d_out);
}